// round 5
// baseline (speedup 1.0000x reference)
#include <cuda_runtime.h>
#include <cstdint>

// ============================================================================
// FrameAugment: out[b,i,f] = softmax_j(noise[b,i,j]*s[b,i]) @ feature[b,j,f]
//   s = (1/(var_row+1e-6)) / max_all(1/(var+1e-6)),  var ddof=1 over F.
// sm_103 baseline-PTX version: fused exp + legacy tf32 mma.sync (no tcgen05,
// which requires the sm_103a PTX target this harness does not use).
// ============================================================================

#define B_ 8
#define S_ 2048
#define F_ 128
#define KC 32
#define NSTAGES (S_ / KC)        // 64

#define PPAD 36                  // P tile row pitch (floats)
#define FPAD 136                 // F tile row pitch (floats)
#define P_BYTES (128 * PPAD * 4) // 18432
#define F_BYTES (KC * FPAD * 4)  // 17408

#define SMEM_RS 0
#define SMEM_P0 512
#define SMEM_P1 (SMEM_P0 + P_BYTES)
#define SMEM_F0 (SMEM_P1 + P_BYTES)
#define SMEM_F1 (SMEM_F0 + F_BYTES)
#define SMEM_TOTAL (SMEM_F1 + F_BYTES)   // 72192 bytes

#define LOG2E 1.4426950408889634f

// ---------------------------------------------------------------------------
// scratch
// ---------------------------------------------------------------------------
__device__ float g_sraw[B_ * S_];   // raw inverse variance per row
__device__ int   g_gmax;            // float-as-int global max (all positive)

// ---------------------------------------------------------------------------
// helpers
// ---------------------------------------------------------------------------
__device__ __forceinline__ float fast_ex2(float x) {
    float y;
    asm("ex2.approx.ftz.f32 %0, %1;" : "=f"(y) : "f"(x));
    return y;
}

__device__ __forceinline__ uint32_t f2tf32(float x) {
    uint32_t r;
    asm("cvt.rna.tf32.f32 %0, %1;" : "=r"(r) : "f"(x));
    return r;
}

// D[16,8] += A[16,8] * B[8,8], tf32 inputs, fp32 accumulate
__device__ __forceinline__ void mma_tf32(float* c, const uint32_t* a, const uint32_t* b) {
    asm volatile(
        "mma.sync.aligned.m16n8k8.row.col.f32.tf32.tf32.f32 "
        "{%0,%1,%2,%3}, {%4,%5,%6,%7}, {%8,%9}, {%0,%1,%2,%3};"
        : "+f"(c[0]), "+f"(c[1]), "+f"(c[2]), "+f"(c[3])
        : "r"(a[0]), "r"(a[1]), "r"(a[2]), "r"(a[3]), "r"(b[0]), "r"(b[1]));
}

// ---------------------------------------------------------------------------
// Kernel 0: reset global max
// ---------------------------------------------------------------------------
__global__ void init_kernel() { g_gmax = 0; }

// ---------------------------------------------------------------------------
// Kernel 1: per-row inverse variance + global max (one warp per row)
// ---------------------------------------------------------------------------
__global__ void __launch_bounds__(256) var_kernel(const float* __restrict__ feat) {
    int row  = blockIdx.x * 8 + (threadIdx.x >> 5);
    int lane = threadIdx.x & 31;
    float4 v = reinterpret_cast<const float4*>(feat + (size_t)row * F_)[lane];
    float s1 = v.x + v.y + v.z + v.w;
    float s2 = v.x * v.x + v.y * v.y + v.z * v.z + v.w * v.w;
    #pragma unroll
    for (int o = 16; o; o >>= 1) {
        s1 += __shfl_xor_sync(0xFFFFFFFFu, s1, o);
        s2 += __shfl_xor_sync(0xFFFFFFFFu, s2, o);
    }
    if (lane == 0) {
        float var = (s2 - s1 * s1 * (1.0f / 128.0f)) * (1.0f / 127.0f);  // ddof=1
        float r = 1.0f / (var + 1e-6f);
        g_sraw[row] = r;
        atomicMax(&g_gmax, __float_as_int(r));   // r > 0 -> int order == float order
    }
}

// ---------------------------------------------------------------------------
// Kernel 2: fused exp + tf32 mma.sync GEMM.
// Grid: 128 CTAs = (b, 128-row i-tile). 256 threads = 8 warps (4 i x 2 f).
// Warp tile: 32 i x 64 f fp32 accumulators. K streamed in 64 chunks of 32,
// double-buffered SMEM, LDG(next) prefetched over MMA(current).
// ---------------------------------------------------------------------------
__global__ void __launch_bounds__(256, 1)
main_kernel(const float* __restrict__ noise, const float* __restrict__ feature,
            float* __restrict__ out) {
    extern __shared__ char smem[];
    float*    rs_s  = reinterpret_cast<float*>(smem + SMEM_RS);
    uint32_t* Pb[2] = { reinterpret_cast<uint32_t*>(smem + SMEM_P0),
                        reinterpret_cast<uint32_t*>(smem + SMEM_P1) };
    uint32_t* Fb[2] = { reinterpret_cast<uint32_t*>(smem + SMEM_F0),
                        reinterpret_cast<uint32_t*>(smem + SMEM_F1) };

    const int tid  = threadIdx.x;
    const int lane = tid & 31;
    const int wid  = tid >> 5;
    const int wi   = wid >> 1;    // 0..3 -> i offset 32*wi
    const int wf   = wid & 1;     // 0..1 -> f offset 64*wf
    const int b    = blockIdx.x >> 4;
    const int i0   = (blockIdx.x & 15) * 128;

    // staging mapping: thread owns rows (rbase + 32g), 16B column slot cq
    const int rbase = tid >> 3;   // 0..31
    const int cq    = tid & 7;    // 0..7

    const float inv_gmax = 1.0f / __int_as_float(g_gmax);
    float sl[4], rs[4];
    #pragma unroll
    for (int g = 0; g < 4; g++) {
        sl[g] = g_sraw[b * S_ + i0 + rbase + 32 * g] * inv_gmax * LOG2E;
        rs[g] = 0.0f;
    }

    const float* nbase = noise + ((size_t)(b * S_ + i0 + rbase)) * S_ + cq * 4;
    const float* fbase = feature + (size_t)b * S_ * F_;

    float acc[2][8][4];
    #pragma unroll
    for (int it = 0; it < 2; it++)
        #pragma unroll
        for (int ft = 0; ft < 8; ft++)
            #pragma unroll
            for (int c = 0; c < 4; c++) acc[it][ft][c] = 0.0f;

    float4 nv[4], fv[4];

    // ---- prologue: load + stage chunk 0 into buffer 0 ----
    #pragma unroll
    for (int g = 0; g < 4; g++)
        nv[g] = *reinterpret_cast<const float4*>(nbase + (size_t)(32 * g) * S_);
    #pragma unroll
    for (int r = 0; r < 4; r++) {
        int e = r * 256 + tid, j = e >> 5, c4 = e & 31;
        fv[r] = *reinterpret_cast<const float4*>(fbase + (size_t)j * F_ + c4 * 4);
    }
    {
        uint32_t* Pp = Pb[0];
        #pragma unroll
        for (int g = 0; g < 4; g++) {
            uint4 t;
            t.x = f2tf32(fast_ex2(nv[g].x * sl[g]));
            t.y = f2tf32(fast_ex2(nv[g].y * sl[g]));
            t.z = f2tf32(fast_ex2(nv[g].z * sl[g]));
            t.w = f2tf32(fast_ex2(nv[g].w * sl[g]));
            rs[g] += (__uint_as_float(t.x) + __uint_as_float(t.y)) +
                     (__uint_as_float(t.z) + __uint_as_float(t.w));
            *reinterpret_cast<uint4*>(&Pp[(rbase + 32 * g) * PPAD + cq * 4]) = t;
        }
        uint32_t* Fp = Fb[0];
        #pragma unroll
        for (int r = 0; r < 4; r++) {
            int e = r * 256 + tid, j = e >> 5, c4 = e & 31;
            uint4 t;
            t.x = f2tf32(fv[r].x); t.y = f2tf32(fv[r].y);
            t.z = f2tf32(fv[r].z); t.w = f2tf32(fv[r].w);
            *reinterpret_cast<uint4*>(&Fp[j * FPAD + c4 * 4]) = t;
        }
    }
    __syncthreads();

    // ---- mainloop ----
    for (int kt = 0; kt < NSTAGES; kt++) {
        const int buf = kt & 1;

        if (kt + 1 < NSTAGES) {          // prefetch next chunk (latency over MMA)
            const int j0 = (kt + 1) * KC;
            #pragma unroll
            for (int g = 0; g < 4; g++)
                nv[g] = *reinterpret_cast<const float4*>(
                    nbase + (size_t)(32 * g) * S_ + j0);
            #pragma unroll
            for (int r = 0; r < 4; r++) {
                int e = r * 256 + tid, j = e >> 5, c4 = e & 31;
                fv[r] = *reinterpret_cast<const float4*>(
                    fbase + (size_t)(j0 + j) * F_ + c4 * 4);
            }
        }

        // MMA on current buffer
        {
            const uint32_t* Ap = Pb[buf];
            const uint32_t* Fp = Fb[buf];
            uint32_t a[2][4][4];
            #pragma unroll
            for (int it = 0; it < 2; it++) {
                int r0 = wi * 32 + it * 16 + (lane >> 2);
                #pragma unroll
                for (int s = 0; s < 4; s++) {
                    int c = s * 8 + (lane & 3);
                    a[it][s][0] = Ap[r0 * PPAD + c];
                    a[it][s][1] = Ap[(r0 + 8) * PPAD + c];
                    a[it][s][2] = Ap[r0 * PPAD + c + 4];
                    a[it][s][3] = Ap[(r0 + 8) * PPAD + c + 4];
                }
            }
            #pragma unroll
            for (int ft = 0; ft < 8; ft++) {
                int n = wf * 64 + ft * 8 + (lane >> 2);
                uint32_t bb[4][2];
                #pragma unroll
                for (int s = 0; s < 4; s++) {
                    int k = s * 8 + (lane & 3);
                    bb[s][0] = Fp[k * FPAD + n];
                    bb[s][1] = Fp[(k + 4) * FPAD + n];
                }
                #pragma unroll
                for (int it = 0; it < 2; it++)
                    #pragma unroll
                    for (int s = 0; s < 4; s++)
                        mma_tf32(acc[it][ft], a[it][s], bb[s]);
            }
        }

        // stage next chunk into the other buffer (last read of it was kt-1)
        if (kt + 1 < NSTAGES) {
            const int nb = buf ^ 1;
            uint32_t* Pp = Pb[nb];
            #pragma unroll
            for (int g = 0; g < 4; g++) {
                uint4 t;
                t.x = f2tf32(fast_ex2(nv[g].x * sl[g]));
                t.y = f2tf32(fast_ex2(nv[g].y * sl[g]));
                t.z = f2tf32(fast_ex2(nv[g].z * sl[g]));
                t.w = f2tf32(fast_ex2(nv[g].w * sl[g]));
                rs[g] += (__uint_as_float(t.x) + __uint_as_float(t.y)) +
                         (__uint_as_float(t.z) + __uint_as_float(t.w));
                *reinterpret_cast<uint4*>(&Pp[(rbase + 32 * g) * PPAD + cq * 4]) = t;
            }
            uint32_t* Fp = Fb[nb];
            #pragma unroll
            for (int r = 0; r < 4; r++) {
                int e = r * 256 + tid, j = e >> 5, c4 = e & 31;
                uint4 t;
                t.x = f2tf32(fv[r].x); t.y = f2tf32(fv[r].y);
                t.z = f2tf32(fv[r].z); t.w = f2tf32(fv[r].w);
                *reinterpret_cast<uint4*>(&Fp[j * FPAD + c4 * 4]) = t;
            }
        }
        __syncthreads();
    }

    // ---- row-sum reduction: 8 threads share a row (same tid>>3) ----
    #pragma unroll
    for (int g = 0; g < 4; g++) {
        #pragma unroll
        for (int o = 1; o < 8; o <<= 1)
            rs[g] += __shfl_xor_sync(0xFFFFFFFFu, rs[g], o);
    }
    if ((tid & 7) == 0) {
        #pragma unroll
        for (int g = 0; g < 4; g++) rs_s[rbase + 32 * g] = rs[g];
    }
    __syncthreads();

    // ---- epilogue: divide by row sum, store ----
    #pragma unroll
    for (int it = 0; it < 2; it++) {
        int r0 = wi * 32 + it * 16 + (lane >> 2);
        int r1 = r0 + 8;
        float inv0 = 1.0f / rs_s[r0];
        float inv1 = 1.0f / rs_s[r1];
        float* o0 = out + (size_t)(b * S_ + i0 + r0) * F_;
        float* o1 = out + (size_t)(b * S_ + i0 + r1) * F_;
        #pragma unroll
        for (int ft = 0; ft < 8; ft++) {
            int n = wf * 64 + ft * 8 + (lane & 3) * 2;
            float2 v0 = { acc[it][ft][0] * inv0, acc[it][ft][1] * inv0 };
            float2 v1 = { acc[it][ft][2] * inv1, acc[it][ft][3] * inv1 };
            *reinterpret_cast<float2*>(o0 + n) = v0;
            *reinterpret_cast<float2*>(o1 + n) = v1;
        }
    }
}

// ---------------------------------------------------------------------------
// launch
// ---------------------------------------------------------------------------
extern "C" void kernel_launch(void* const* d_in, const int* in_sizes, int n_in,
                              void* d_out, int out_size) {
    static bool attr_set = false;
    if (!attr_set) {
        cudaFuncSetAttribute(main_kernel,
                             cudaFuncAttributeMaxDynamicSharedMemorySize, SMEM_TOTAL);
        attr_set = true;
    }

    // metadata order: feature [B,S,F], noise [B,S,S] (defensive size check)
    const float* feature = (const float*)d_in[0];
    const float* noise   = (const float*)d_in[1];
    if (n_in >= 2 && in_sizes[0] > in_sizes[1]) {
        feature = (const float*)d_in[1];
        noise   = (const float*)d_in[0];
    }
    float* out = (float*)d_out;

    init_kernel<<<1, 1>>>();
    var_kernel<<<(B_ * S_) / 8, 256>>>(feature);
    main_kernel<<<B_ * (S_ / 128), 256, SMEM_TOTAL>>>(noise, feature, out);
}

// round 6
// speedup vs baseline: 1.0939x; 1.0939x over previous
#include <cuda_runtime.h>
#include <cstdint>

// ============================================================================
// FrameAugment: out[b,i,f] = softmax_j(noise[b,i,j]*s[b,i]) @ feature[b,j,f]
//   s = (1/(var_row+1e-6)) / max_all(1/(var+1e-6)),  var ddof=1 over F.
// sm_103 baseline-PTX: fused exp + legacy tf32 mma.sync.m16n8k8.
// R6: 512 thr/CTA (4 warps/SMSP), ldmatrix A-fragments, no init kernel.
// ============================================================================

#define B_ 8
#define S_ 2048
#define F_ 128
#define KC 32
#define NSTAGES (S_ / KC)        // 64

#define PPAD 36                  // P tile row pitch (floats): LDSM conflict-free
#define FPAD 136                 // F tile row pitch (floats): LDS conflict-free
#define P_BYTES (128 * PPAD * 4) // 18432
#define F_BYTES (KC * FPAD * 4)  // 17408

#define SMEM_RS 0
#define SMEM_P0 512
#define SMEM_P1 (SMEM_P0 + P_BYTES)
#define SMEM_F0 (SMEM_P1 + P_BYTES)
#define SMEM_F1 (SMEM_F0 + F_BYTES)
#define SMEM_TOTAL (SMEM_F1 + F_BYTES)   // 72192 bytes

#define NVARBLK ((B_ * S_) / 8)          // 2048

#define LOG2E 1.4426950408889634f

// ---------------------------------------------------------------------------
// scratch
// ---------------------------------------------------------------------------
__device__ float g_sraw[B_ * S_];     // raw inverse variance per row
__device__ float g_bmax[NVARBLK];     // per-block maxes (overwritten every run)
__device__ float g_gmax_f;            // global max (plain store, no reset needed)

// ---------------------------------------------------------------------------
// helpers
// ---------------------------------------------------------------------------
__device__ __forceinline__ uint32_t smem_u32(const void* p) {
    uint32_t a;
    asm("{ .reg .u64 t; cvta.to.shared.u64 t, %1; cvt.u32.u64 %0, t; }" : "=r"(a) : "l"(p));
    return a;
}

__device__ __forceinline__ float fast_ex2(float x) {
    float y;
    asm("ex2.approx.ftz.f32 %0, %1;" : "=f"(y) : "f"(x));
    return y;
}

__device__ __forceinline__ uint32_t f2tf32(float x) {
    uint32_t r;
    asm("cvt.rna.tf32.f32 %0, %1;" : "=r"(r) : "f"(x));
    return r;
}

// D[16,8] += A[16,8] * B[8,8], tf32 inputs, fp32 accumulate
__device__ __forceinline__ void mma_tf32(float* c, const uint32_t* a, const uint32_t* b) {
    asm volatile(
        "mma.sync.aligned.m16n8k8.row.col.f32.tf32.tf32.f32 "
        "{%0,%1,%2,%3}, {%4,%5,%6,%7}, {%8,%9}, {%0,%1,%2,%3};"
        : "+f"(c[0]), "+f"(c[1]), "+f"(c[2]), "+f"(c[3])
        : "r"(a[0]), "r"(a[1]), "r"(a[2]), "r"(a[3]), "r"(b[0]), "r"(b[1]));
}

// load one m16n8k8 tf32 A fragment (4 regs) via ldmatrix x4 (b16 view)
__device__ __forceinline__ void ldsm_x4(uint32_t* a, uint32_t addr) {
    asm volatile(
        "ldmatrix.sync.aligned.m8n8.x4.shared.b16 {%0,%1,%2,%3}, [%4];"
        : "=r"(a[0]), "=r"(a[1]), "=r"(a[2]), "=r"(a[3]) : "r"(addr));
}

// ---------------------------------------------------------------------------
// Kernel 1: per-row inverse variance + per-block max (one warp per row)
// ---------------------------------------------------------------------------
__global__ void __launch_bounds__(256) var_kernel(const float* __restrict__ feat) {
    __shared__ float wmax[8];
    int wrp  = threadIdx.x >> 5;
    int lane = threadIdx.x & 31;
    int row  = blockIdx.x * 8 + wrp;
    float4 v = reinterpret_cast<const float4*>(feat + (size_t)row * F_)[lane];
    float s1 = v.x + v.y + v.z + v.w;
    float s2 = v.x * v.x + v.y * v.y + v.z * v.z + v.w * v.w;
    #pragma unroll
    for (int o = 16; o; o >>= 1) {
        s1 += __shfl_xor_sync(0xFFFFFFFFu, s1, o);
        s2 += __shfl_xor_sync(0xFFFFFFFFu, s2, o);
    }
    if (lane == 0) {
        float var = (s2 - s1 * s1 * (1.0f / 128.0f)) * (1.0f / 127.0f);  // ddof=1
        float r = 1.0f / (var + 1e-6f);
        g_sraw[row] = r;
        wmax[wrp] = r;
    }
    __syncthreads();
    if (threadIdx.x == 0) {
        float m = wmax[0];
        #pragma unroll
        for (int k = 1; k < 8; k++) m = fmaxf(m, wmax[k]);
        g_bmax[blockIdx.x] = m;
    }
}

// ---------------------------------------------------------------------------
// Kernel 1b: reduce block maxes -> g_gmax_f (plain store; graph-replay safe)
// ---------------------------------------------------------------------------
__global__ void __launch_bounds__(256) reduce_kernel() {
    __shared__ float wmax[8];
    int tid = threadIdx.x, lane = tid & 31;
    float m = 0.0f;
    #pragma unroll
    for (int k = 0; k < NVARBLK / 256; k++) m = fmaxf(m, g_bmax[tid + k * 256]);
    #pragma unroll
    for (int o = 16; o; o >>= 1) m = fmaxf(m, __shfl_xor_sync(0xFFFFFFFFu, m, o));
    if (lane == 0) wmax[tid >> 5] = m;
    __syncthreads();
    if (tid == 0) {
        float g = wmax[0];
        #pragma unroll
        for (int k = 1; k < 8; k++) g = fmaxf(g, wmax[k]);
        g_gmax_f = g;
    }
}

// ---------------------------------------------------------------------------
// Kernel 2: fused exp + tf32 mma.sync GEMM.
// Grid: 128 CTAs = (b, 128-row i-tile). 512 threads = 16 warps (4 i x 4 f).
// Warp tile: 32 i x 32 f fp32 accumulators. K in 64 chunks of 32,
// double-buffered SMEM; A frags via ldmatrix; LDG(next) prefetched over MMA.
// ---------------------------------------------------------------------------
__global__ void __launch_bounds__(512, 1)
main_kernel(const float* __restrict__ noise, const float* __restrict__ feature,
            float* __restrict__ out) {
    extern __shared__ char smem[];
    float* rs_s = reinterpret_cast<float*>(smem + SMEM_RS);
    const uint32_t sbase = smem_u32(smem);
    uint32_t* Fb[2] = { reinterpret_cast<uint32_t*>(smem + SMEM_F0),
                        reinterpret_cast<uint32_t*>(smem + SMEM_F1) };
    uint32_t* Pw[2] = { reinterpret_cast<uint32_t*>(smem + SMEM_P0),
                        reinterpret_cast<uint32_t*>(smem + SMEM_P1) };
    const uint32_t Pa_base[2] = { sbase + SMEM_P0, sbase + SMEM_P1 };

    const int tid  = threadIdx.x;
    const int lane = tid & 31;
    const int wid  = tid >> 5;        // 0..15
    const int wi   = wid >> 2;        // i block (32 rows each)
    const int wf   = wid & 3;         // f block (32 cols each)
    const int b    = blockIdx.x >> 4;
    const int i0   = (blockIdx.x & 15) * 128;

    // staging: thread owns one P row, two 16B column slots (cq, cq+4)
    const int prow = tid >> 2;        // 0..127
    const int cq   = tid & 3;         // 0..3
    // F staging: two float4 per thread
    const int jf   = tid >> 5;        // 0..15 (and +16 for second)
    const int c4   = tid & 31;        // 0..31

    const float sl = g_sraw[b * S_ + i0 + prow] * (1.0f / g_gmax_f) * LOG2E;
    float rs = 0.0f;

    const float* nrow  = noise + ((size_t)(b * S_ + i0 + prow)) * S_;
    const float* fbase = feature + (size_t)b * S_ * F_;

    // ldmatrix per-lane byte offset within P buffer (for this warp)
    const uint32_t a_lane_off =
        (uint32_t)(((wi * 32 + (lane & 15)) * PPAD + (lane >> 4) * 4) * 4);

    // P store word offsets
    const int p_off0 = prow * PPAD + cq * 4;
    const int p_off1 = p_off0 + 16;
    // F store word offsets
    const int f_off0 = jf * FPAD + c4 * 4;
    const int f_off1 = f_off0 + 16 * FPAD;

    float acc[2][4][4];
    #pragma unroll
    for (int it = 0; it < 2; it++)
        #pragma unroll
        for (int ft = 0; ft < 4; ft++)
            #pragma unroll
            for (int c = 0; c < 4; c++) acc[it][ft][c] = 0.0f;

    float4 nv0, nv1, fv0, fv1;

    // ---- prologue: load + stage chunk 0 into buffer 0 ----
    nv0 = *reinterpret_cast<const float4*>(nrow + cq * 4);
    nv1 = *reinterpret_cast<const float4*>(nrow + (cq + 4) * 4);
    fv0 = *reinterpret_cast<const float4*>(fbase + (size_t)jf * F_ + c4 * 4);
    fv1 = *reinterpret_cast<const float4*>(fbase + (size_t)(jf + 16) * F_ + c4 * 4);
    {
        uint32_t* Pp = Pw[0];
        uint4 t0, t1;
        t0.x = f2tf32(fast_ex2(nv0.x * sl)); t0.y = f2tf32(fast_ex2(nv0.y * sl));
        t0.z = f2tf32(fast_ex2(nv0.z * sl)); t0.w = f2tf32(fast_ex2(nv0.w * sl));
        t1.x = f2tf32(fast_ex2(nv1.x * sl)); t1.y = f2tf32(fast_ex2(nv1.y * sl));
        t1.z = f2tf32(fast_ex2(nv1.z * sl)); t1.w = f2tf32(fast_ex2(nv1.w * sl));
        rs += (__uint_as_float(t0.x) + __uint_as_float(t0.y)) +
              (__uint_as_float(t0.z) + __uint_as_float(t0.w)) +
              (__uint_as_float(t1.x) + __uint_as_float(t1.y)) +
              (__uint_as_float(t1.z) + __uint_as_float(t1.w));
        *reinterpret_cast<uint4*>(&Pp[p_off0]) = t0;
        *reinterpret_cast<uint4*>(&Pp[p_off1]) = t1;
        uint32_t* Fp = Fb[0];
        uint4 u0, u1;
        u0.x = f2tf32(fv0.x); u0.y = f2tf32(fv0.y);
        u0.z = f2tf32(fv0.z); u0.w = f2tf32(fv0.w);
        u1.x = f2tf32(fv1.x); u1.y = f2tf32(fv1.y);
        u1.z = f2tf32(fv1.z); u1.w = f2tf32(fv1.w);
        *reinterpret_cast<uint4*>(&Fp[f_off0]) = u0;
        *reinterpret_cast<uint4*>(&Fp[f_off1]) = u1;
    }
    __syncthreads();

    // ---- mainloop ----
    for (int kt = 0; kt < NSTAGES; kt++) {
        const int buf = kt & 1;

        if (kt + 1 < NSTAGES) {          // prefetch next chunk into registers
            const int j0 = (kt + 1) * KC;
            nv0 = *reinterpret_cast<const float4*>(nrow + j0 + cq * 4);
            nv1 = *reinterpret_cast<const float4*>(nrow + j0 + (cq + 4) * 4);
            fv0 = *reinterpret_cast<const float4*>(
                fbase + (size_t)(j0 + jf) * F_ + c4 * 4);
            fv1 = *reinterpret_cast<const float4*>(
                fbase + (size_t)(j0 + jf + 16) * F_ + c4 * 4);
        }

        // MMA on current buffer
        {
            const uint32_t Pa = Pa_base[buf];
            const uint32_t* Fp = Fb[buf];
            uint32_t A[2][4][4];
            #pragma unroll
            for (int it = 0; it < 2; it++)
                #pragma unroll
                for (int s = 0; s < 4; s++)
                    ldsm_x4(A[it][s], Pa + a_lane_off +
                            (uint32_t)(it * 16 * PPAD * 4 + s * 32));
            #pragma unroll
            for (int ft = 0; ft < 4; ft++) {
                const int nn = wf * 32 + ft * 8 + (lane >> 2);
                uint32_t bb[4][2];
                #pragma unroll
                for (int s = 0; s < 4; s++) {
                    bb[s][0] = Fp[(s * 8 + (lane & 3)) * FPAD + nn];
                    bb[s][1] = Fp[(s * 8 + 4 + (lane & 3)) * FPAD + nn];
                }
                #pragma unroll
                for (int it = 0; it < 2; it++)
                    #pragma unroll
                    for (int s = 0; s < 4; s++)
                        mma_tf32(acc[it][ft], A[it][s], bb[s]);
            }
        }

        // stage next chunk into the other buffer
        if (kt + 1 < NSTAGES) {
            uint32_t* Pp = Pw[buf ^ 1];
            uint4 t0, t1;
            t0.x = f2tf32(fast_ex2(nv0.x * sl)); t0.y = f2tf32(fast_ex2(nv0.y * sl));
            t0.z = f2tf32(fast_ex2(nv0.z * sl)); t0.w = f2tf32(fast_ex2(nv0.w * sl));
            t1.x = f2tf32(fast_ex2(nv1.x * sl)); t1.y = f2tf32(fast_ex2(nv1.y * sl));
            t1.z = f2tf32(fast_ex2(nv1.z * sl)); t1.w = f2tf32(fast_ex2(nv1.w * sl));
            rs += (__uint_as_float(t0.x) + __uint_as_float(t0.y)) +
                  (__uint_as_float(t0.z) + __uint_as_float(t0.w)) +
                  (__uint_as_float(t1.x) + __uint_as_float(t1.y)) +
                  (__uint_as_float(t1.z) + __uint_as_float(t1.w));
            *reinterpret_cast<uint4*>(&Pp[p_off0]) = t0;
            *reinterpret_cast<uint4*>(&Pp[p_off1]) = t1;
            uint32_t* Fp = Fb[buf ^ 1];
            uint4 u0, u1;
            u0.x = f2tf32(fv0.x); u0.y = f2tf32(fv0.y);
            u0.z = f2tf32(fv0.z); u0.w = f2tf32(fv0.w);
            u1.x = f2tf32(fv1.x); u1.y = f2tf32(fv1.y);
            u1.z = f2tf32(fv1.z); u1.w = f2tf32(fv1.w);
            *reinterpret_cast<uint4*>(&Fp[f_off0]) = u0;
            *reinterpret_cast<uint4*>(&Fp[f_off1]) = u1;
        }
        __syncthreads();
    }

    // ---- row sums: 4 threads share a row ----
    rs += __shfl_xor_sync(0xFFFFFFFFu, rs, 1);
    rs += __shfl_xor_sync(0xFFFFFFFFu, rs, 2);
    if ((tid & 3) == 0) rs_s[prow] = rs;
    __syncthreads();

    // ---- epilogue: divide by row sum, store ----
    #pragma unroll
    for (int it = 0; it < 2; it++) {
        const int r0 = wi * 32 + it * 16 + (lane >> 2);
        const int r1 = r0 + 8;
        const float inv0 = 1.0f / rs_s[r0];
        const float inv1 = 1.0f / rs_s[r1];
        float* o0 = out + (size_t)(b * S_ + i0 + r0) * F_;
        float* o1 = out + (size_t)(b * S_ + i0 + r1) * F_;
        #pragma unroll
        for (int ft = 0; ft < 4; ft++) {
            const int n = wf * 32 + ft * 8 + (lane & 3) * 2;
            float2 v0 = { acc[it][ft][0] * inv0, acc[it][ft][1] * inv0 };
            float2 v1 = { acc[it][ft][2] * inv1, acc[it][ft][3] * inv1 };
            *reinterpret_cast<float2*>(o0 + n) = v0;
            *reinterpret_cast<float2*>(o1 + n) = v1;
        }
    }
}

// ---------------------------------------------------------------------------
// launch
// ---------------------------------------------------------------------------
extern "C" void kernel_launch(void* const* d_in, const int* in_sizes, int n_in,
                              void* d_out, int out_size) {
    static bool attr_set = false;
    if (!attr_set) {
        cudaFuncSetAttribute(main_kernel,
                             cudaFuncAttributeMaxDynamicSharedMemorySize, SMEM_TOTAL);
        attr_set = true;
    }

    // metadata order: feature [B,S,F], noise [B,S,S] (defensive size check)
    const float* feature = (const float*)d_in[0];
    const float* noise   = (const float*)d_in[1];
    if (n_in >= 2 && in_sizes[0] > in_sizes[1]) {
        feature = (const float*)d_in[1];
        noise   = (const float*)d_in[0];
    }
    float* out = (float*)d_out;

    var_kernel<<<NVARBLK, 256>>>(feature);
    reduce_kernel<<<1, 256>>>();
    main_kernel<<<B_ * (S_ / 128), 512, SMEM_TOTAL>>>(noise, feature, out);
}